// round 1
// baseline (speedup 1.0000x reference)
#include <cuda_runtime.h>

#define B 8
#define S 2048
#define DM 1024
#define DK 64
#define ROWS (B * S)

// ---------------- scratch (device globals; no allocation allowed) ----------
__device__ float g_Q[ROWS * DK];            // 4 MB
__device__ float g_K[ROWS * DK];            // 4 MB
__device__ float g_V[ROWS * DM];            // 64 MB
__device__ float g_M[ROWS];                 // row max of scaled scores
__device__ float g_L[ROWS];                 // row sum of exp(s - m)

// ===========================================================================
// Kernel 1: fused Q|K projection.  C[ROWS,128] where cols 0..63 = X@Wq+bq,
// cols 64..127 = X@Wk+bk.  BM=128, BN=128, BK=16, 256 threads, 8x8 microtile.
// ===========================================================================
__global__ __launch_bounds__(256) void qk_proj_kernel(
    const float* __restrict__ X,
    const float* __restrict__ Wq, const float* __restrict__ bq,
    const float* __restrict__ Wk, const float* __restrict__ bk)
{
    __shared__ float sA[16][128];   // sA[k][m]  (A transposed on load)
    __shared__ float sB[16][128];   // sB[k][n]

    const int r0  = blockIdx.x * 128;
    const int tid = threadIdx.x;
    const int tx  = tid & 15;   // col group (8 cols)
    const int ty  = tid >> 4;   // row group (8 rows)

    float acc[8][8];
#pragma unroll
    for (int i = 0; i < 8; i++)
#pragma unroll
        for (int j = 0; j < 8; j++) acc[i][j] = 0.f;

    for (int kc = 0; kc < DM; kc += 16) {
        // --- load A tile (128 rows x 16 k) transposed, float4 per thread x2
#pragma unroll
        for (int it = 0; it < 2; it++) {
            int lin = tid + it * 256;          // 0..511 (512 float4)
            int m   = lin >> 2;                // 0..127
            int k4  = lin & 3;                 // 0..3
            float4 v = *reinterpret_cast<const float4*>(
                &X[(r0 + m) * DM + kc + k4 * 4]);
            sA[k4 * 4 + 0][m] = v.x;
            sA[k4 * 4 + 1][m] = v.y;
            sA[k4 * 4 + 2][m] = v.z;
            sA[k4 * 4 + 3][m] = v.w;
        }
        // --- load B tile (16 k x 128 n): n<64 from Wq, else Wk, float4 x2
#pragma unroll
        for (int it = 0; it < 2; it++) {
            int lin = tid + it * 256;          // 0..511 (512 float4)
            int kk  = lin >> 5;                // 0..15
            int n4  = lin & 31;                // 0..31
            const float* src = (n4 < 16)
                ? &Wq[(kc + kk) * DK + n4 * 4]
                : &Wk[(kc + kk) * DK + (n4 - 16) * 4];
            reinterpret_cast<float4*>(&sB[kk][0])[n4] =
                *reinterpret_cast<const float4*>(src);
        }
        __syncthreads();
#pragma unroll
        for (int kk = 0; kk < 16; kk++) {
            float4 a0 = *reinterpret_cast<const float4*>(&sA[kk][ty * 8]);
            float4 a1 = *reinterpret_cast<const float4*>(&sA[kk][ty * 8 + 4]);
            float4 b0 = *reinterpret_cast<const float4*>(&sB[kk][tx * 8]);
            float4 b1 = *reinterpret_cast<const float4*>(&sB[kk][tx * 8 + 4]);
            float a[8] = {a0.x, a0.y, a0.z, a0.w, a1.x, a1.y, a1.z, a1.w};
            float b[8] = {b0.x, b0.y, b0.z, b0.w, b1.x, b1.y, b1.z, b1.w};
#pragma unroll
            for (int i = 0; i < 8; i++)
#pragma unroll
                for (int j = 0; j < 8; j++) acc[i][j] += a[i] * b[j];
        }
        __syncthreads();
    }
    // epilogue: bias + split store to g_Q / g_K
#pragma unroll
    for (int i = 0; i < 8; i++) {
        int r = r0 + ty * 8 + i;
#pragma unroll
        for (int j = 0; j < 8; j++) {
            int n = tx * 8 + j;
            if (n < 64) g_Q[r * DK + n]        = acc[i][j] + bq[n];
            else        g_K[r * DK + (n - 64)] = acc[i][j] + bk[n - 64];
        }
    }
}

// ===========================================================================
// Kernel 2: V projection.  g_V[ROWS,1024] = X @ Wv + bv.
// BM=128, BN=128, BK=16, 256 threads, 8x8 microtile.
// ===========================================================================
__global__ __launch_bounds__(256) void v_proj_kernel(
    const float* __restrict__ X,
    const float* __restrict__ Wv, const float* __restrict__ bv)
{
    __shared__ float sA[16][128];
    __shared__ float sB[16][128];

    const int r0  = blockIdx.x * 128;
    const int nc  = blockIdx.y * 128;
    const int tid = threadIdx.x;
    const int tx  = tid & 15;
    const int ty  = tid >> 4;

    float acc[8][8];
#pragma unroll
    for (int i = 0; i < 8; i++)
#pragma unroll
        for (int j = 0; j < 8; j++) acc[i][j] = 0.f;

    for (int kc = 0; kc < DM; kc += 16) {
#pragma unroll
        for (int it = 0; it < 2; it++) {
            int lin = tid + it * 256;
            int m   = lin >> 2;
            int k4  = lin & 3;
            float4 v = *reinterpret_cast<const float4*>(
                &X[(r0 + m) * DM + kc + k4 * 4]);
            sA[k4 * 4 + 0][m] = v.x;
            sA[k4 * 4 + 1][m] = v.y;
            sA[k4 * 4 + 2][m] = v.z;
            sA[k4 * 4 + 3][m] = v.w;
        }
#pragma unroll
        for (int it = 0; it < 2; it++) {
            int lin = tid + it * 256;
            int kk  = lin >> 5;
            int n4  = lin & 31;
            reinterpret_cast<float4*>(&sB[kk][0])[n4] =
                *reinterpret_cast<const float4*>(
                    &Wv[(kc + kk) * DM + nc + n4 * 4]);
        }
        __syncthreads();
#pragma unroll
        for (int kk = 0; kk < 16; kk++) {
            float4 a0 = *reinterpret_cast<const float4*>(&sA[kk][ty * 8]);
            float4 a1 = *reinterpret_cast<const float4*>(&sA[kk][ty * 8 + 4]);
            float4 b0 = *reinterpret_cast<const float4*>(&sB[kk][tx * 8]);
            float4 b1 = *reinterpret_cast<const float4*>(&sB[kk][tx * 8 + 4]);
            float a[8] = {a0.x, a0.y, a0.z, a0.w, a1.x, a1.y, a1.z, a1.w};
            float b[8] = {b0.x, b0.y, b0.z, b0.w, b1.x, b1.y, b1.z, b1.w};
#pragma unroll
            for (int i = 0; i < 8; i++)
#pragma unroll
                for (int j = 0; j < 8; j++) acc[i][j] += a[i] * b[j];
        }
        __syncthreads();
    }
#pragma unroll
    for (int i = 0; i < 8; i++) {
        int r = r0 + ty * 8 + i;
#pragma unroll
        for (int j = 0; j < 8; j++) {
            int n = nc + tx * 8 + j;
            g_V[r * DM + n] = acc[i][j] + bv[n];
        }
    }
}

// ===========================================================================
// Kernel 3 (pass A): per-row softmax stats m_i, l_i over causal keys.
// Block: 32 queries, 256 threads.  ty = query row (32), tx = key subgroup (8,
// 4 keys each).  Online (m,l) per thread, butterfly-combined over tx.
// ===========================================================================
__global__ __launch_bounds__(256) void softmax_stats_kernel()
{
    __shared__ float sQ[32][65];
    __shared__ float sK[32][65];

    const int b    = blockIdx.y;
    const int q0   = blockIdx.x * 32;
    const int tid  = threadIdx.x;
    const int ty   = tid >> 3;   // 0..31 query row
    const int tx   = tid & 7;    // 0..7  key subgroup
    const int base = b * S;

    for (int lin = tid; lin < 32 * 64; lin += 256) {
        int r = lin >> 6, d = lin & 63;
        sQ[r][d] = g_Q[(base + q0 + r) * DK + d];
    }

    float m = -1e30f, l = 0.f;
    const int iglob  = q0 + ty;
    const int ntiles = q0 / 32 + 1;

    for (int t = 0; t < ntiles; t++) {
        const int k0 = t * 32;
        __syncthreads();
        for (int lin = tid; lin < 32 * 64; lin += 256) {
            int r = lin >> 6, d = lin & 63;
            sK[r][d] = g_K[(base + k0 + r) * DK + d];
        }
        __syncthreads();

        float s[4] = {0.f, 0.f, 0.f, 0.f};
#pragma unroll 8
        for (int d = 0; d < 64; d++) {
            float qv = sQ[ty][d];
#pragma unroll
            for (int jj = 0; jj < 4; jj++)
                s[jj] += qv * sK[tx * 4 + jj][d];
        }
        float tmax = -1e30f;
#pragma unroll
        for (int jj = 0; jj < 4; jj++) {
            int jg = k0 + tx * 4 + jj;
            s[jj] = (jg <= iglob) ? s[jj] * 0.125f : -1e30f;
            tmax  = fmaxf(tmax, s[jj]);
        }
        float newm = fmaxf(m, tmax);
        float add  = 0.f;
#pragma unroll
        for (int jj = 0; jj < 4; jj++) add += __expf(s[jj] - newm);
        l = l * __expf(m - newm) + add;
        m = newm;
    }

    // butterfly combine across the 8 tx lanes of this row (contiguous lanes)
#pragma unroll
    for (int off = 1; off < 8; off <<= 1) {
        float mo = __shfl_xor_sync(0xffffffffu, m, off);
        float lo = __shfl_xor_sync(0xffffffffu, l, off);
        float M  = fmaxf(m, mo);
        l = l * __expf(m - M) + lo * __expf(mo - M);
        m = M;
    }
    if (tx == 0) {
        g_M[base + iglob] = m;
        g_L[base + iglob] = l;
    }
}

// ===========================================================================
// Kernel 4 (pass B): O[:, dchunk] = (exp(S - m) / l) @ V[:, dchunk].
// Grid (S/32, 4 dchunks of 256, B).  128 threads.
// Score phase: jgrp = tid&3 (8 keys), qrow = tid>>2 (32 rows).
// PV phase:    tx = tid&31 (8 d-cols), ty = tid>>5 (8 q-rows), 8x8 acc.
// K tile and V tile share the `buf` smem region (sequenced by syncthreads).
// ===========================================================================
__global__ __launch_bounds__(128) void attn_pv_kernel(float* __restrict__ out)
{
    __shared__ float sQ[32][65];
    __shared__ float sP[32][33];
    __shared__ float buf[32 * 256];   // K as buf[j*65+d], V as buf[k*256+c]

    const int b      = blockIdx.z;
    const int dc0    = blockIdx.y * 256;
    const int q0     = blockIdx.x * 32;
    const int tid    = threadIdx.x;
    const int base   = b * S;

    const int tx   = tid & 31;   // PV d-group
    const int ty   = tid >> 5;   // PV q-group (0..3)
    const int jgrp = tid & 3;    // score key-group (8 keys)
    const int qrow = tid >> 2;   // score query row (0..31)

    for (int lin = tid; lin < 32 * 64; lin += 128) {
        int r = lin >> 6, d = lin & 63;
        sQ[r][d] = g_Q[(base + q0 + r) * DK + d];
    }

    float acc[8][8];
#pragma unroll
    for (int i = 0; i < 8; i++)
#pragma unroll
        for (int j = 0; j < 8; j++) acc[i][j] = 0.f;

    const float mrow  = g_M[base + q0 + qrow];
    const int  iglob  = q0 + qrow;
    const int  ntiles = q0 / 32 + 1;
    __syncthreads();   // sQ ready

    for (int t = 0; t < ntiles; t++) {
        const int k0 = t * 32;
        // ---- K tile into buf -------------------------------------------
        for (int lin = tid; lin < 32 * 64; lin += 128) {
            int r = lin >> 6, d = lin & 63;
            buf[r * 65 + d] = g_K[(base + k0 + r) * DK + d];
        }
        __syncthreads();
        // ---- scores -> sP (unnormalized exp; /l folded into epilogue) --
        float s[8];
#pragma unroll
        for (int j = 0; j < 8; j++) s[j] = 0.f;
#pragma unroll 8
        for (int d = 0; d < 64; d++) {
            float qv = sQ[qrow][d];
#pragma unroll
            for (int jj = 0; jj < 8; jj++)
                s[jj] += qv * buf[(jgrp * 8 + jj) * 65 + d];
        }
#pragma unroll
        for (int jj = 0; jj < 8; jj++) {
            int jg = k0 + jgrp * 8 + jj;
            sP[qrow][jgrp * 8 + jj] =
                (jg <= iglob) ? __expf(s[jj] * 0.125f - mrow) : 0.f;
        }
        __syncthreads();   // sP written, K consumed
        // ---- V tile into buf (float4) ----------------------------------
        {
            float4* bufv = reinterpret_cast<float4*>(buf);
            for (int lin = tid; lin < 2048; lin += 128) {
                int r = lin >> 6, c4 = lin & 63;
                bufv[r * 64 + c4] = *reinterpret_cast<const float4*>(
                    &g_V[(base + k0 + r) * DM + dc0 + c4 * 4]);
            }
        }
        __syncthreads();
        // ---- PV accumulate ---------------------------------------------
#pragma unroll 2
        for (int k = 0; k < 32; k++) {
            float p[8];
#pragma unroll
            for (int i = 0; i < 8; i++) p[i] = sP[ty * 8 + i][k];
            float4 v0 = *reinterpret_cast<const float4*>(&buf[k * 256 + tx * 8]);
            float4 v1 = *reinterpret_cast<const float4*>(&buf[k * 256 + tx * 8 + 4]);
            float vv[8] = {v0.x, v0.y, v0.z, v0.w, v1.x, v1.y, v1.z, v1.w};
#pragma unroll
            for (int i = 0; i < 8; i++)
#pragma unroll
                for (int j = 0; j < 8; j++) acc[i][j] += p[i] * vv[j];
        }
        __syncthreads();   // buf & sP consumed before next tile
    }

    // ---- epilogue: scale by 1/l, store ---------------------------------
#pragma unroll
    for (int i = 0; i < 8; i++) {
        int   r    = q0 + ty * 8 + i;
        float linv = 1.0f / g_L[base + r];
        float4 o0, o1;
        o0.x = acc[i][0] * linv; o0.y = acc[i][1] * linv;
        o0.z = acc[i][2] * linv; o0.w = acc[i][3] * linv;
        o1.x = acc[i][4] * linv; o1.y = acc[i][5] * linv;
        o1.z = acc[i][6] * linv; o1.w = acc[i][7] * linv;
        float* dst = &out[(size_t)(base + r) * DM + dc0 + tx * 8];
        *reinterpret_cast<float4*>(dst)     = o0;
        *reinterpret_cast<float4*>(dst + 4) = o1;
    }
}

// ===========================================================================
extern "C" void kernel_launch(void* const* d_in, const int* in_sizes, int n_in,
                              void* d_out, int out_size)
{
    const float* X  = (const float*)d_in[0];
    const float* Wq = (const float*)d_in[1];
    const float* bq = (const float*)d_in[2];
    const float* Wk = (const float*)d_in[3];
    const float* bk = (const float*)d_in[4];
    const float* Wv = (const float*)d_in[5];
    const float* bv = (const float*)d_in[6];
    float* out = (float*)d_out;

    qk_proj_kernel<<<ROWS / 128, 256>>>(X, Wq, bq, Wk, bk);
    v_proj_kernel<<<dim3(ROWS / 128, DM / 128), 256>>>(X, Wv, bv);
    softmax_stats_kernel<<<dim3(S / 32, B), 256>>>();
    attn_pv_kernel<<<dim3(S / 32, 4, B), 128>>>(out);
}

// round 3
// speedup vs baseline: 1.2664x; 1.2664x over previous
#include <cuda_runtime.h>
#include <cstdint>

#define B 8
#define S 2048
#define DM 1024
#define DK 64
#define ROWS (B * S)

// ---------------- scratch (device globals; no allocation allowed) ----------
__device__ float g_Q[ROWS * DK];            // 4 MB
__device__ float g_K[ROWS * DK];            // 4 MB
__device__ float g_V[ROWS * DM];            // 64 MB
__device__ float g_M[ROWS];
__device__ float g_L[ROWS];
__device__ float g_WvT[DM * DM];            // Wv^T, K-major, tf32-rounded (4 MB)
__device__ float g_WqkT[128 * DM];          // [Wq|Wk]^T, K-major, tf32-rounded
__device__ float g_bqk[128];

// ======================= helpers ==========================================
__device__ __forceinline__ uint32_t f2tf32(float f) {
    uint32_t o;
    asm("cvt.rna.tf32.f32 %0, %1;" : "=r"(o) : "f"(f));
    return o;
}

__device__ __forceinline__ void mma_tf32(float c[4], const uint32_t a[4],
                                         const uint32_t b[2]) {
    asm volatile(
        "mma.sync.aligned.m16n8k8.row.col.f32.tf32.tf32.f32 "
        "{%0,%1,%2,%3}, {%4,%5,%6,%7}, {%8,%9}, {%0,%1,%2,%3};"
        : "+f"(c[0]), "+f"(c[1]), "+f"(c[2]), "+f"(c[3])
        : "r"(a[0]), "r"(a[1]), "r"(a[2]), "r"(a[3]), "r"(b[0]), "r"(b[1]));
}

// ===========================================================================
// Prep: tiled transposes into K-major weight copies (values tf32-rounded)
// ===========================================================================
__global__ __launch_bounds__(256) void transpose_wv_kernel(const float* __restrict__ Wv)
{
    __shared__ float t[32][33];
    const int k0 = blockIdx.x * 32, n0 = blockIdx.y * 32;
    const int tx = threadIdx.x, ty = threadIdx.y;
#pragma unroll
    for (int i = 0; i < 32; i += 8)
        t[ty + i][tx] = Wv[(k0 + ty + i) * DM + n0 + tx];
    __syncthreads();
#pragma unroll
    for (int i = 0; i < 32; i += 8)
        g_WvT[(n0 + ty + i) * DM + k0 + tx] =
            __uint_as_float(f2tf32(t[tx][ty + i]));
}

__global__ __launch_bounds__(256) void prep_qk_kernel(
    const float* __restrict__ Wq, const float* __restrict__ bq,
    const float* __restrict__ Wk, const float* __restrict__ bk)
{
    __shared__ float t[32][33];
    const int k0 = blockIdx.x * 32, n0 = blockIdx.y * 32;
    const int tx = threadIdx.x, ty = threadIdx.y;
    const int n = n0 + tx;
#pragma unroll
    for (int i = 0; i < 32; i += 8) {
        int k = k0 + ty + i;
        t[ty + i][tx] = (n < 64) ? Wq[k * DK + n] : Wk[k * DK + (n - 64)];
    }
    __syncthreads();
#pragma unroll
    for (int i = 0; i < 32; i += 8)
        g_WqkT[(n0 + ty + i) * DM + k0 + tx] =
            __uint_as_float(f2tf32(t[tx][ty + i]));
    if (blockIdx.x == 0 && blockIdx.y == 0) {
        int id = ty * 32 + tx;
        if (id < 128) g_bqk[id] = (id < 64) ? bq[id] : bk[id - 64];
    }
}

// ===========================================================================
// tf32 mma.sync GEMM: C[128x128 tile] = A[.,1024] @ Bt[.,1024]^T (+bias)
// mode 0: Bt=g_WvT,  C -> g_V (+bv)
// mode 1: Bt=g_WqkT, C -> split g_Q | g_K (+g_bqk), grid.y == 1
// BM=128 BN=128 BK=16, 256 thr (8 warps, 2x4), warp tile 64x32 (m16n8k8).
// Smem rows padded to 20 words: frag-load bank pattern (20m+k)%32 conflict-free.
// ===========================================================================
#define PAD 20
__global__ __launch_bounds__(256) void gemm_tc_kernel(
    const float* __restrict__ A, const float* __restrict__ bv, int mode)
{
    __shared__ uint32_t sA[128 * PAD];    // [m][k] tf32
    __shared__ uint32_t sB[128 * PAD];    // [n][k] tf32

    const float* Bt = mode ? g_WqkT : g_WvT;

    const int r0   = blockIdx.x * 128;
    const int nc   = blockIdx.y * 128;
    const int tid  = threadIdx.x;
    const int wid  = tid >> 5;
    const int lane = tid & 31;
    const int wm   = (wid >> 2) * 64;     // warp m offset
    const int wn   = (wid & 3) * 32;      // warp n offset
    const int lr   = lane >> 2;           // fragment row lane  (0..7)
    const int lc   = lane & 3;            // fragment col lane  (0..3)

    float acc[4][4][4];
#pragma unroll
    for (int mi = 0; mi < 4; mi++)
#pragma unroll
        for (int ni = 0; ni < 4; ni++)
#pragma unroll
            for (int r = 0; r < 4; r++) acc[mi][ni][r] = 0.f;

    for (int kc = 0; kc < DM; kc += 16) {
        // ---- stage A tile: 128m x 16k, float4 along k, cvt to tf32 -------
#pragma unroll
        for (int it = 0; it < 2; it++) {
            int lin = tid + it * 256;          // 0..511
            int m = lin >> 2, k4 = lin & 3;
            float4 v = *reinterpret_cast<const float4*>(
                &A[(size_t)(r0 + m) * DM + kc + k4 * 4]);
            uint32_t* dst = &sA[m * PAD + k4 * 4];
            dst[0] = f2tf32(v.x); dst[1] = f2tf32(v.y);
            dst[2] = f2tf32(v.z); dst[3] = f2tf32(v.w);
        }
        // ---- stage B tile: 128n x 16k (Bt already tf32-rounded) ----------
#pragma unroll
        for (int it = 0; it < 2; it++) {
            int lin = tid + it * 256;
            int n = lin >> 2, k4 = lin & 3;
            float4 v = *reinterpret_cast<const float4*>(
                &Bt[(size_t)(nc + n) * DM + kc + k4 * 4]);
            uint32_t* dst = &sB[n * PAD + k4 * 4];
            dst[0] = __float_as_uint(v.x); dst[1] = __float_as_uint(v.y);
            dst[2] = __float_as_uint(v.z); dst[3] = __float_as_uint(v.w);
        }
        __syncthreads();

#pragma unroll
        for (int ks = 0; ks < 2; ks++) {
            const int k0 = ks * 8;
            uint32_t a[4][4], b[4][2];
#pragma unroll
            for (int mi = 0; mi < 4; mi++) {
                const uint32_t* p = &sA[(wm + mi * 16 + lr) * PAD + k0 + lc];
                a[mi][0] = p[0];
                a[mi][1] = p[8 * PAD];
                a[mi][2] = p[4];
                a[mi][3] = p[8 * PAD + 4];
            }
#pragma unroll
            for (int ni = 0; ni < 4; ni++) {
                const uint32_t* p = &sB[(wn + ni * 8 + lr) * PAD + k0 + lc];
                b[ni][0] = p[0];
                b[ni][1] = p[4];
            }
#pragma unroll
            for (int mi = 0; mi < 4; mi++)
#pragma unroll
                for (int ni = 0; ni < 4; ni++)
                    mma_tf32(acc[mi][ni], a[mi], b[ni]);
        }
        __syncthreads();
    }

    // ---- epilogue: c0,c1 -> (row, 2*lc), c2,c3 -> (row+8, 2*lc) ----------
#pragma unroll
    for (int mi = 0; mi < 4; mi++) {
#pragma unroll
        for (int ni = 0; ni < 4; ni++) {
#pragma unroll
            for (int h = 0; h < 2; h++) {      // h=0: rows, h=1: rows+8
                int row = r0 + wm + mi * 16 + lr + h * 8;
                int col = wn + ni * 8 + 2 * lc;   // within 0..127
                float v0 = acc[mi][ni][h * 2 + 0];
                float v1 = acc[mi][ni][h * 2 + 1];
                if (mode == 0) {
                    float2 o = {v0 + bv[nc + col], v1 + bv[nc + col + 1]};
                    *reinterpret_cast<float2*>(
                        &g_V[(size_t)row * DM + nc + col]) = o;
                } else {
                    float w0 = v0 + g_bqk[col];
                    float w1 = v1 + g_bqk[col + 1];
                    if (col < 64) {
                        float2 o = {w0, w1};
                        *reinterpret_cast<float2*>(&g_Q[(size_t)row * DK + col]) = o;
                    } else {
                        float2 o = {w0, w1};
                        *reinterpret_cast<float2*>(
                            &g_K[(size_t)row * DK + (col - 64)]) = o;
                    }
                }
            }
        }
    }
}

// ===========================================================================
// Kernel 3 (pass A): per-row softmax stats m_i, l_i over causal keys.
// ===========================================================================
__global__ __launch_bounds__(256) void softmax_stats_kernel()
{
    __shared__ float sQ[32][65];
    __shared__ float sK[32][65];

    const int b    = blockIdx.y;
    const int q0   = blockIdx.x * 32;
    const int tid  = threadIdx.x;
    const int ty   = tid >> 3;
    const int tx   = tid & 7;
    const int base = b * S;

    for (int lin = tid; lin < 32 * 64; lin += 256) {
        int r = lin >> 6, d = lin & 63;
        sQ[r][d] = g_Q[(base + q0 + r) * DK + d];
    }

    float m = -1e30f, l = 0.f;
    const int iglob  = q0 + ty;
    const int ntiles = q0 / 32 + 1;

    for (int t = 0; t < ntiles; t++) {
        const int k0 = t * 32;
        __syncthreads();
        for (int lin = tid; lin < 32 * 64; lin += 256) {
            int r = lin >> 6, d = lin & 63;
            sK[r][d] = g_K[(base + k0 + r) * DK + d];
        }
        __syncthreads();

        float s[4] = {0.f, 0.f, 0.f, 0.f};
#pragma unroll 8
        for (int d = 0; d < 64; d++) {
            float qv = sQ[ty][d];
#pragma unroll
            for (int jj = 0; jj < 4; jj++)
                s[jj] += qv * sK[tx * 4 + jj][d];
        }
        float tmax = -1e30f;
#pragma unroll
        for (int jj = 0; jj < 4; jj++) {
            int jg = k0 + tx * 4 + jj;
            s[jj] = (jg <= iglob) ? s[jj] * 0.125f : -1e30f;
            tmax  = fmaxf(tmax, s[jj]);
        }
        float newm = fmaxf(m, tmax);
        float add  = 0.f;
#pragma unroll
        for (int jj = 0; jj < 4; jj++) add += __expf(s[jj] - newm);
        l = l * __expf(m - newm) + add;
        m = newm;
    }

#pragma unroll
    for (int off = 1; off < 8; off <<= 1) {
        float mo = __shfl_xor_sync(0xffffffffu, m, off);
        float lo = __shfl_xor_sync(0xffffffffu, l, off);
        float M  = fmaxf(m, mo);
        l = l * __expf(m - M) + lo * __expf(mo - M);
        m = M;
    }
    if (tx == 0) {
        g_M[base + iglob] = m;
        g_L[base + iglob] = l;
    }
}

// ===========================================================================
// Kernel 4 (pass B): O[:, dchunk] = (exp(S - m) / l) @ V[:, dchunk].
// ===========================================================================
__global__ __launch_bounds__(128) void attn_pv_kernel(float* __restrict__ out)
{
    __shared__ float sQ[32][65];
    __shared__ float sP[32][33];
    __shared__ float buf[32 * 256];

    const int b      = blockIdx.z;
    const int dc0    = blockIdx.y * 256;
    const int q0     = blockIdx.x * 32;
    const int tid    = threadIdx.x;
    const int base   = b * S;

    const int tx   = tid & 31;
    const int ty   = tid >> 5;
    const int jgrp = tid & 3;
    const int qrow = tid >> 2;

    for (int lin = tid; lin < 32 * 64; lin += 128) {
        int r = lin >> 6, d = lin & 63;
        sQ[r][d] = g_Q[(base + q0 + r) * DK + d];
    }

    float acc[8][8];
#pragma unroll
    for (int i = 0; i < 8; i++)
#pragma unroll
        for (int j = 0; j < 8; j++) acc[i][j] = 0.f;

    const float mrow  = g_M[base + q0 + qrow];
    const int  iglob  = q0 + qrow;
    const int  ntiles = q0 / 32 + 1;
    __syncthreads();

    for (int t = 0; t < ntiles; t++) {
        const int k0 = t * 32;
        for (int lin = tid; lin < 32 * 64; lin += 128) {
            int r = lin >> 6, d = lin & 63;
            buf[r * 65 + d] = g_K[(base + k0 + r) * DK + d];
        }
        __syncthreads();
        float s[8];
#pragma unroll
        for (int j = 0; j < 8; j++) s[j] = 0.f;
#pragma unroll 8
        for (int d = 0; d < 64; d++) {
            float qv = sQ[qrow][d];
#pragma unroll
            for (int jj = 0; jj < 8; jj++)
                s[jj] += qv * buf[(jgrp * 8 + jj) * 65 + d];
        }
#pragma unroll
        for (int jj = 0; jj < 8; jj++) {
            int jg = k0 + jgrp * 8 + jj;
            sP[qrow][jgrp * 8 + jj] =
                (jg <= iglob) ? __expf(s[jj] * 0.125f - mrow) : 0.f;
        }
        __syncthreads();
        {
            float4* bufv = reinterpret_cast<float4*>(buf);
            for (int lin = tid; lin < 2048; lin += 128) {
                int r = lin >> 6, c4 = lin & 63;
                bufv[r * 64 + c4] = *reinterpret_cast<const float4*>(
                    &g_V[(base + k0 + r) * DM + dc0 + c4 * 4]);
            }
        }
        __syncthreads();
#pragma unroll 2
        for (int k = 0; k < 32; k++) {
            float p[8];
#pragma unroll
            for (int i = 0; i < 8; i++) p[i] = sP[ty * 8 + i][k];
            float4 v0 = *reinterpret_cast<const float4*>(&buf[k * 256 + tx * 8]);
            float4 v1 = *reinterpret_cast<const float4*>(&buf[k * 256 + tx * 8 + 4]);
            float vv[8] = {v0.x, v0.y, v0.z, v0.w, v1.x, v1.y, v1.z, v1.w};
#pragma unroll
            for (int i = 0; i < 8; i++)
#pragma unroll
                for (int j = 0; j < 8; j++) acc[i][j] += p[i] * vv[j];
        }
        __syncthreads();
    }

#pragma unroll
    for (int i = 0; i < 8; i++) {
        int   r    = q0 + ty * 8 + i;
        float linv = 1.0f / g_L[base + r];
        float4 o0, o1;
        o0.x = acc[i][0] * linv; o0.y = acc[i][1] * linv;
        o0.z = acc[i][2] * linv; o0.w = acc[i][3] * linv;
        o1.x = acc[i][4] * linv; o1.y = acc[i][5] * linv;
        o1.z = acc[i][6] * linv; o1.w = acc[i][7] * linv;
        float* dst = &out[(size_t)(base + r) * DM + dc0 + tx * 8];
        *reinterpret_cast<float4*>(dst)     = o0;
        *reinterpret_cast<float4*>(dst + 4) = o1;
    }
}

// ===========================================================================
extern "C" void kernel_launch(void* const* d_in, const int* in_sizes, int n_in,
                              void* d_out, int out_size)
{
    const float* X  = (const float*)d_in[0];
    const float* Wq = (const float*)d_in[1];
    const float* bq = (const float*)d_in[2];
    const float* Wk = (const float*)d_in[3];
    const float* bk = (const float*)d_in[4];
    const float* Wv = (const float*)d_in[5];
    const float* bv = (const float*)d_in[6];
    float* out = (float*)d_out;

    transpose_wv_kernel<<<dim3(32, 32), dim3(32, 8)>>>(Wv);
    prep_qk_kernel<<<dim3(32, 4), dim3(32, 8)>>>(Wq, bq, Wk, bk);
    gemm_tc_kernel<<<dim3(128, 1), 256>>>(X, nullptr, 1);   // Q|K projection
    gemm_tc_kernel<<<dim3(128, 8), 256>>>(X, bv, 0);        // V projection
    softmax_stats_kernel<<<dim3(S / 32, B), 256>>>();
    attn_pv_kernel<<<dim3(S / 32, 4, B), 128>>>(out);
}

// round 4
// speedup vs baseline: 3.8287x; 3.0234x over previous
#include <cuda_runtime.h>
#include <cstdint>

#define B 8
#define S 2048
#define DM 1024
#define DK 64
#define ROWS (B * S)

// ---------------- scratch (device globals; no allocation allowed) ----------
__device__ float g_Q[ROWS * DK];            // 4 MB
__device__ float g_K[ROWS * DK];            // 4 MB
__device__ float g_V[ROWS * DM];            // 64 MB
__device__ float g_L[ROWS];
__device__ float g_P[(size_t)ROWS * S];     // 134 MB score / prob matrix
__device__ float g_WvT[DM * DM];            // Wv^T, K-major, tf32-rounded
__device__ float g_WqkT[128 * DM];          // [Wq|Wk]^T, K-major, tf32-rounded
__device__ float g_bqk[128];

// ======================= helpers ==========================================
__device__ __forceinline__ uint32_t f2tf32(float f) {
    uint32_t o;
    asm("cvt.rna.tf32.f32 %0, %1;" : "=r"(o) : "f"(f));
    return o;
}

__device__ __forceinline__ void mma_tf32(float c[4], const uint32_t a[4],
                                         const uint32_t b[2]) {
    asm volatile(
        "mma.sync.aligned.m16n8k8.row.col.f32.tf32.tf32.f32 "
        "{%0,%1,%2,%3}, {%4,%5,%6,%7}, {%8,%9}, {%0,%1,%2,%3};"
        : "+f"(c[0]), "+f"(c[1]), "+f"(c[2]), "+f"(c[3])
        : "r"(a[0]), "r"(a[1]), "r"(a[2]), "r"(a[3]), "r"(b[0]), "r"(b[1]));
}

// ===========================================================================
// Prep: tiled transposes into K-major weight copies (values tf32-rounded)
// ===========================================================================
__global__ __launch_bounds__(256) void transpose_wv_kernel(const float* __restrict__ Wv)
{
    __shared__ float t[32][33];
    const int k0 = blockIdx.x * 32, n0 = blockIdx.y * 32;
    const int tx = threadIdx.x, ty = threadIdx.y;
#pragma unroll
    for (int i = 0; i < 32; i += 8)
        t[ty + i][tx] = Wv[(k0 + ty + i) * DM + n0 + tx];
    __syncthreads();
#pragma unroll
    for (int i = 0; i < 32; i += 8)
        g_WvT[(n0 + ty + i) * DM + k0 + tx] =
            __uint_as_float(f2tf32(t[tx][ty + i]));
}

__global__ __launch_bounds__(256) void prep_qk_kernel(
    const float* __restrict__ Wq, const float* __restrict__ bq,
    const float* __restrict__ Wk, const float* __restrict__ bk)
{
    __shared__ float t[32][33];
    const int k0 = blockIdx.x * 32, n0 = blockIdx.y * 32;
    const int tx = threadIdx.x, ty = threadIdx.y;
    const int n = n0 + tx;
#pragma unroll
    for (int i = 0; i < 32; i += 8) {
        int k = k0 + ty + i;
        t[ty + i][tx] = (n < 64) ? Wq[k * DK + n] : Wk[k * DK + (n - 64)];
    }
    __syncthreads();
#pragma unroll
    for (int i = 0; i < 32; i += 8)
        g_WqkT[(n0 + ty + i) * DM + k0 + tx] =
            __uint_as_float(f2tf32(t[tx][ty + i]));
    if (blockIdx.x == 0 && blockIdx.y == 0) {
        int id = ty * 32 + tx;
        if (id < 128) g_bqk[id] = (id < 64) ? bq[id] : bk[id - 64];
    }
}

// ===========================================================================
// tf32 mma.sync GEMM (projections). mode 0: g_V (+bv), mode 1: g_Q|g_K.
// BM=128 BN=128 BK=16, 256 thr (8 warps, 2x4), warp tile 64x32 (m16n8k8).
// ===========================================================================
#define PAD 20
__global__ __launch_bounds__(256) void gemm_tc_kernel(
    const float* __restrict__ A, const float* __restrict__ bv, int mode)
{
    __shared__ uint32_t sA[128 * PAD];
    __shared__ uint32_t sB[128 * PAD];

    const float* Bt = mode ? g_WqkT : g_WvT;

    const int r0   = blockIdx.x * 128;
    const int nc   = blockIdx.y * 128;
    const int tid  = threadIdx.x;
    const int wid  = tid >> 5;
    const int lane = tid & 31;
    const int wm   = (wid >> 2) * 64;
    const int wn   = (wid & 3) * 32;
    const int lr   = lane >> 2;
    const int lc   = lane & 3;

    float acc[4][4][4];
#pragma unroll
    for (int mi = 0; mi < 4; mi++)
#pragma unroll
        for (int ni = 0; ni < 4; ni++)
#pragma unroll
            for (int r = 0; r < 4; r++) acc[mi][ni][r] = 0.f;

    for (int kc = 0; kc < DM; kc += 16) {
#pragma unroll
        for (int it = 0; it < 2; it++) {
            int lin = tid + it * 256;
            int m = lin >> 2, k4 = lin & 3;
            float4 v = *reinterpret_cast<const float4*>(
                &A[(size_t)(r0 + m) * DM + kc + k4 * 4]);
            uint32_t* dst = &sA[m * PAD + k4 * 4];
            dst[0] = f2tf32(v.x); dst[1] = f2tf32(v.y);
            dst[2] = f2tf32(v.z); dst[3] = f2tf32(v.w);
        }
#pragma unroll
        for (int it = 0; it < 2; it++) {
            int lin = tid + it * 256;
            int n = lin >> 2, k4 = lin & 3;
            float4 v = *reinterpret_cast<const float4*>(
                &Bt[(size_t)(nc + n) * DM + kc + k4 * 4]);
            uint32_t* dst = &sB[n * PAD + k4 * 4];
            dst[0] = __float_as_uint(v.x); dst[1] = __float_as_uint(v.y);
            dst[2] = __float_as_uint(v.z); dst[3] = __float_as_uint(v.w);
        }
        __syncthreads();

#pragma unroll
        for (int ks = 0; ks < 2; ks++) {
            const int k0 = ks * 8;
            uint32_t a[4][4], b[4][2];
#pragma unroll
            for (int mi = 0; mi < 4; mi++) {
                const uint32_t* p = &sA[(wm + mi * 16 + lr) * PAD + k0 + lc];
                a[mi][0] = p[0];
                a[mi][1] = p[8 * PAD];
                a[mi][2] = p[4];
                a[mi][3] = p[8 * PAD + 4];
            }
#pragma unroll
            for (int ni = 0; ni < 4; ni++) {
                const uint32_t* p = &sB[(wn + ni * 8 + lr) * PAD + k0 + lc];
                b[ni][0] = p[0];
                b[ni][1] = p[4];
            }
#pragma unroll
            for (int mi = 0; mi < 4; mi++)
#pragma unroll
                for (int ni = 0; ni < 4; ni++)
                    mma_tf32(acc[mi][ni], a[mi], b[ni]);
        }
        __syncthreads();
    }

#pragma unroll
    for (int mi = 0; mi < 4; mi++) {
#pragma unroll
        for (int ni = 0; ni < 4; ni++) {
#pragma unroll
            for (int h = 0; h < 2; h++) {
                int row = r0 + wm + mi * 16 + lr + h * 8;
                int col = wn + ni * 8 + 2 * lc;
                float v0 = acc[mi][ni][h * 2 + 0];
                float v1 = acc[mi][ni][h * 2 + 1];
                if (mode == 0) {
                    float2 o = {v0 + bv[nc + col], v1 + bv[nc + col + 1]};
                    *reinterpret_cast<float2*>(
                        &g_V[(size_t)row * DM + nc + col]) = o;
                } else {
                    float w0 = v0 + g_bqk[col];
                    float w1 = v1 + g_bqk[col + 1];
                    float2 o = {w0, w1};
                    if (col < 64)
                        *reinterpret_cast<float2*>(&g_Q[(size_t)row * DK + col]) = o;
                    else
                        *reinterpret_cast<float2*>(
                            &g_K[(size_t)row * DK + (col - 64)]) = o;
                }
            }
        }
    }
}

// ===========================================================================
// score_kernel: one 128x128 causal tile of S = Q K^T / 8 per CTA (raw fp32
// to g_P, masked entries = -1e30).  Triangular grid: blockIdx.x = tile id.
// Contraction dk=64, staged in 4 chunks of 16.  Same 8-warp 2x4 layout.
// ===========================================================================
__global__ __launch_bounds__(256) void score_kernel()
{
    __shared__ uint32_t sA[128 * PAD];
    __shared__ uint32_t sB[128 * PAD];

    // decode triangular tile index -> (qt, kt), kt <= qt
    int i = blockIdx.x;
    int qt = (int)((sqrtf(8.f * (float)i + 1.f) - 1.f) * 0.5f);
    while ((qt + 1) * (qt + 2) / 2 <= i) qt++;
    while (qt * (qt + 1) / 2 > i) qt--;
    const int kt = i - qt * (qt + 1) / 2;

    const int b     = blockIdx.y;
    const int qbase = b * S + qt * 128;
    const int kbase = b * S + kt * 128;

    const int tid  = threadIdx.x;
    const int wid  = tid >> 5;
    const int lane = tid & 31;
    const int wm   = (wid >> 2) * 64;
    const int wn   = (wid & 3) * 32;
    const int lr   = lane >> 2;
    const int lc   = lane & 3;

    float acc[4][4][4];
#pragma unroll
    for (int mi = 0; mi < 4; mi++)
#pragma unroll
        for (int ni = 0; ni < 4; ni++)
#pragma unroll
            for (int r = 0; r < 4; r++) acc[mi][ni][r] = 0.f;

    for (int kc = 0; kc < DK; kc += 16) {
#pragma unroll
        for (int it = 0; it < 2; it++) {
            int lin = tid + it * 256;
            int m = lin >> 2, k4 = lin & 3;
            float4 v = *reinterpret_cast<const float4*>(
                &g_Q[(size_t)(qbase + m) * DK + kc + k4 * 4]);
            uint32_t* dst = &sA[m * PAD + k4 * 4];
            dst[0] = f2tf32(v.x); dst[1] = f2tf32(v.y);
            dst[2] = f2tf32(v.z); dst[3] = f2tf32(v.w);
        }
#pragma unroll
        for (int it = 0; it < 2; it++) {
            int lin = tid + it * 256;
            int n = lin >> 2, k4 = lin & 3;
            float4 v = *reinterpret_cast<const float4*>(
                &g_K[(size_t)(kbase + n) * DK + kc + k4 * 4]);
            uint32_t* dst = &sB[n * PAD + k4 * 4];
            dst[0] = f2tf32(v.x); dst[1] = f2tf32(v.y);
            dst[2] = f2tf32(v.z); dst[3] = f2tf32(v.w);
        }
        __syncthreads();

#pragma unroll
        for (int ks = 0; ks < 2; ks++) {
            const int k0 = ks * 8;
            uint32_t a[4][4], b2[4][2];
#pragma unroll
            for (int mi = 0; mi < 4; mi++) {
                const uint32_t* p = &sA[(wm + mi * 16 + lr) * PAD + k0 + lc];
                a[mi][0] = p[0];
                a[mi][1] = p[8 * PAD];
                a[mi][2] = p[4];
                a[mi][3] = p[8 * PAD + 4];
            }
#pragma unroll
            for (int ni = 0; ni < 4; ni++) {
                const uint32_t* p = &sB[(wn + ni * 8 + lr) * PAD + k0 + lc];
                b2[ni][0] = p[0];
                b2[ni][1] = p[4];
            }
#pragma unroll
            for (int mi = 0; mi < 4; mi++)
#pragma unroll
                for (int ni = 0; ni < 4; ni++)
                    mma_tf32(acc[mi][ni], a[mi], b2[ni]);
        }
        __syncthreads();
    }

    // scale, mask, store raw scores
#pragma unroll
    for (int mi = 0; mi < 4; mi++) {
#pragma unroll
        for (int ni = 0; ni < 4; ni++) {
#pragma unroll
            for (int h = 0; h < 2; h++) {
                int qrow = qt * 128 + wm + mi * 16 + lr + h * 8;  // in-batch
                int kcol = kt * 128 + wn + ni * 8 + 2 * lc;
                float v0 = acc[mi][ni][h * 2 + 0] * 0.125f;
                float v1 = acc[mi][ni][h * 2 + 1] * 0.125f;
                if (kcol > qrow)     v0 = -1e30f;
                if (kcol + 1 > qrow) v1 = -1e30f;
                float2 o = {v0, v1};
                *reinterpret_cast<float2*>(
                    &g_P[(size_t)(b * S + qrow) * S + kcol]) = o;
            }
        }
    }
}

// ===========================================================================
// rowexp_kernel: warp per row.  m = max(row), P = exp(P - m), l = sum,
// zero pad region up to the 128-tile boundary so pv_kernel reads clean tiles.
// ===========================================================================
__global__ __launch_bounds__(256) void rowexp_kernel()
{
    const int tid  = threadIdx.x;
    const int wid  = tid >> 5;
    const int lane = tid & 31;
    const int row  = blockIdx.x * 8 + wid;        // 0..ROWS-1
    const int q    = row & (S - 1);               // in-batch query index
    float* P = &g_P[(size_t)row * S];
    const int L    = q + 1;
    const int kend = ((q >> 7) + 1) << 7;

    float m = -1e30f;
    for (int j = lane; j < L; j += 32) m = fmaxf(m, P[j]);
#pragma unroll
    for (int off = 16; off > 0; off >>= 1)
        m = fmaxf(m, __shfl_xor_sync(0xffffffffu, m, off));

    float l = 0.f;
    for (int j = lane; j < L; j += 32) {
        float e = __expf(P[j] - m);
        P[j] = e;
        l += e;
    }
#pragma unroll
    for (int off = 16; off > 0; off >>= 1)
        l += __shfl_xor_sync(0xffffffffu, l, off);

    for (int j = L + lane; j < kend; j += 32) P[j] = 0.f;

    if (lane == 0) g_L[row] = l;
}

// ===========================================================================
// pv_kernel: O[128q x 128d tile] = (P_exp/l) @ V.  Causal k-loop.
// BM=128 BN=128 BK=32.  sP stride 36, sV [k][d] stride 136 (conflict-free).
// ===========================================================================
#define STP 36
#define STV 136
__global__ __launch_bounds__(256) void pv_kernel(float* __restrict__ out)
{
    __shared__ uint32_t sP[128 * STP];
    __shared__ uint32_t sV[32 * STV];

    const int qt    = blockIdx.x;
    const int dc0   = blockIdx.y * 128;
    const int b     = blockIdx.z;
    const int base  = b * S;
    const int qbase = base + qt * 128;

    const int tid  = threadIdx.x;
    const int wid  = tid >> 5;
    const int lane = tid & 31;
    const int wm   = (wid >> 2) * 64;
    const int wn   = (wid & 3) * 32;
    const int lr   = lane >> 2;
    const int lc   = lane & 3;

    float acc[4][4][4];
#pragma unroll
    for (int mi = 0; mi < 4; mi++)
#pragma unroll
        for (int ni = 0; ni < 4; ni++)
#pragma unroll
            for (int r = 0; r < 4; r++) acc[mi][ni][r] = 0.f;

    const int kmax = (qt + 1) * 128;
    for (int kc = 0; kc < kmax; kc += 32) {
        // ---- stage P tile [128q x 32k] ----------------------------------
#pragma unroll
        for (int it = 0; it < 4; it++) {
            int lin = tid + it * 256;          // 0..1023
            int m = lin >> 3, k4 = lin & 7;
            float4 v = *reinterpret_cast<const float4*>(
                &g_P[(size_t)(qbase + m) * S + kc + k4 * 4]);
            uint32_t* dst = &sP[m * STP + k4 * 4];
            dst[0] = f2tf32(v.x); dst[1] = f2tf32(v.y);
            dst[2] = f2tf32(v.z); dst[3] = f2tf32(v.w);
        }
        // ---- stage V tile [32k x 128d] ----------------------------------
#pragma unroll
        for (int it = 0; it < 4; it++) {
            int lin = tid + it * 256;
            int k = lin >> 5, d4 = lin & 31;
            float4 v = *reinterpret_cast<const float4*>(
                &g_V[(size_t)(base + kc + k) * DM + dc0 + d4 * 4]);
            uint32_t* dst = &sV[k * STV + d4 * 4];
            dst[0] = f2tf32(v.x); dst[1] = f2tf32(v.y);
            dst[2] = f2tf32(v.z); dst[3] = f2tf32(v.w);
        }
        __syncthreads();

#pragma unroll
        for (int ks = 0; ks < 4; ks++) {
            const int k0 = ks * 8;
            uint32_t a[4][4], b2[4][2];
#pragma unroll
            for (int mi = 0; mi < 4; mi++) {
                const uint32_t* p = &sP[(wm + mi * 16 + lr) * STP + k0 + lc];
                a[mi][0] = p[0];
                a[mi][1] = p[8 * STP];
                a[mi][2] = p[4];
                a[mi][3] = p[8 * STP + 4];
            }
#pragma unroll
            for (int ni = 0; ni < 4; ni++) {
                int n = wn + ni * 8 + lr;
                b2[ni][0] = sV[(k0 + lc) * STV + n];
                b2[ni][1] = sV[(k0 + lc + 4) * STV + n];
            }
#pragma unroll
            for (int mi = 0; mi < 4; mi++)
#pragma unroll
                for (int ni = 0; ni < 4; ni++)
                    mma_tf32(acc[mi][ni], a[mi], b2[ni]);
        }
        __syncthreads();
    }

    // ---- epilogue: scale by 1/l, write out -------------------------------
#pragma unroll
    for (int mi = 0; mi < 4; mi++) {
#pragma unroll
        for (int h = 0; h < 2; h++) {
            int qrow = qt * 128 + wm + mi * 16 + lr + h * 8;   // in-batch
            float linv = 1.0f / g_L[base + qrow];
#pragma unroll
            for (int ni = 0; ni < 4; ni++) {
                int col = dc0 + wn + ni * 8 + 2 * lc;
                float2 o = {acc[mi][ni][h * 2 + 0] * linv,
                            acc[mi][ni][h * 2 + 1] * linv};
                *reinterpret_cast<float2*>(
                    &out[(size_t)(base + qrow) * DM + col]) = o;
            }
        }
    }
}

// ===========================================================================
extern "C" void kernel_launch(void* const* d_in, const int* in_sizes, int n_in,
                              void* d_out, int out_size)
{
    const float* X  = (const float*)d_in[0];
    const float* Wq = (const float*)d_in[1];
    const float* bq = (const float*)d_in[2];
    const float* Wk = (const float*)d_in[3];
    const float* bk = (const float*)d_in[4];
    const float* Wv = (const float*)d_in[5];
    const float* bv = (const float*)d_in[6];
    float* out = (float*)d_out;

    transpose_wv_kernel<<<dim3(32, 32), dim3(32, 8)>>>(Wv);
    prep_qk_kernel<<<dim3(32, 4), dim3(32, 8)>>>(Wq, bq, Wk, bk);
    gemm_tc_kernel<<<dim3(128, 1), 256>>>(X, nullptr, 1);   // Q|K projection
    gemm_tc_kernel<<<dim3(128, 8), 256>>>(X, bv, 0);        // V projection
    score_kernel<<<dim3(136, 8), 256>>>();                  // S = QK^T/8 (causal)
    rowexp_kernel<<<ROWS / 8, 256>>>();                     // softmax (in place)
    pv_kernel<<<dim3(S / 128, DM / 128, B), 256>>>(out);    // O = P V / l
}

// round 5
// speedup vs baseline: 4.1218x; 1.0765x over previous
#include <cuda_runtime.h>
#include <cstdint>

#define B 8
#define S 2048
#define DM 1024
#define DK 64
#define ROWS (B * S)

// ---------------- scratch (device globals; no allocation allowed) ----------
__device__ float g_Q[ROWS * DK];            // 4 MB
__device__ float g_K[ROWS * DK];            // 4 MB
__device__ float g_V[ROWS * DM];            // 64 MB
__device__ float g_L[ROWS];
__device__ float g_P[(size_t)ROWS * S];     // 134 MB score / prob matrix
__device__ float g_WvT[DM * DM];            // Wv^T, K-major, tf32-rounded
__device__ float g_WqkT[128 * DM];          // [Wq|Wk]^T, K-major, tf32-rounded
__device__ float g_bqk[128];

// ======================= helpers ==========================================
__device__ __forceinline__ uint32_t f2tf32(float f) {
    uint32_t o;
    asm("cvt.rna.tf32.f32 %0, %1;" : "=r"(o) : "f"(f));
    return o;
}

__device__ __forceinline__ void mma_tf32(float c[4], const uint32_t a[4],
                                         const uint32_t b[2]) {
    asm volatile(
        "mma.sync.aligned.m16n8k8.row.col.f32.tf32.tf32.f32 "
        "{%0,%1,%2,%3}, {%4,%5,%6,%7}, {%8,%9}, {%0,%1,%2,%3};"
        : "+f"(c[0]), "+f"(c[1]), "+f"(c[2]), "+f"(c[3])
        : "r"(a[0]), "r"(a[1]), "r"(a[2]), "r"(a[3]), "r"(b[0]), "r"(b[1]));
}

// ===========================================================================
// Prep: tiled transposes into K-major weight copies (values tf32-rounded)
// ===========================================================================
__global__ __launch_bounds__(256) void transpose_wv_kernel(const float* __restrict__ Wv)
{
    __shared__ float t[32][33];
    const int k0 = blockIdx.x * 32, n0 = blockIdx.y * 32;
    const int tx = threadIdx.x, ty = threadIdx.y;
#pragma unroll
    for (int i = 0; i < 32; i += 8)
        t[ty + i][tx] = Wv[(k0 + ty + i) * DM + n0 + tx];
    __syncthreads();
#pragma unroll
    for (int i = 0; i < 32; i += 8)
        g_WvT[(n0 + ty + i) * DM + k0 + tx] =
            __uint_as_float(f2tf32(t[tx][ty + i]));
}

__global__ __launch_bounds__(256) void prep_qk_kernel(
    const float* __restrict__ Wq, const float* __restrict__ bq,
    const float* __restrict__ Wk, const float* __restrict__ bk)
{
    __shared__ float t[32][33];
    const int k0 = blockIdx.x * 32, n0 = blockIdx.y * 32;
    const int tx = threadIdx.x, ty = threadIdx.y;
    const int n = n0 + tx;
#pragma unroll
    for (int i = 0; i < 32; i += 8) {
        int k = k0 + ty + i;
        t[ty + i][tx] = (n < 64) ? Wq[k * DK + n] : Wk[k * DK + (n - 64)];
    }
    __syncthreads();
#pragma unroll
    for (int i = 0; i < 32; i += 8)
        g_WqkT[(n0 + ty + i) * DM + k0 + tx] =
            __uint_as_float(f2tf32(t[tx][ty + i]));
    if (blockIdx.x == 0 && blockIdx.y == 0) {
        int id = ty * 32 + tx;
        if (id < 128) g_bqk[id] = (id < 64) ? bq[id] : bk[id - 64];
    }
}

// ===========================================================================
// tf32 mma.sync GEMM (projections), double-buffered smem + reg prefetch.
// mode 0: g_V (+bv), mode 1: g_Q|g_K.
// BM=128 BN=128 BK=16, 256 thr (8 warps, 2x4), warp tile 64x32 (m16n8k8).
// ===========================================================================
#define PAD 20
__global__ __launch_bounds__(256, 2) void gemm_tc_kernel(
    const float* __restrict__ A, const float* __restrict__ bv, int mode)
{
    __shared__ uint32_t sA[2][128 * PAD];
    __shared__ uint32_t sB[2][128 * PAD];

    const float* Bt = mode ? g_WqkT : g_WvT;

    const int r0   = blockIdx.x * 128;
    const int nc   = blockIdx.y * 128;
    const int tid  = threadIdx.x;
    const int wid  = tid >> 5;
    const int lane = tid & 31;
    const int wm   = (wid >> 2) * 64;
    const int wn   = (wid & 3) * 32;
    const int lr   = lane >> 2;
    const int lc   = lane & 3;

    float acc[4][4][4];
#pragma unroll
    for (int mi = 0; mi < 4; mi++)
#pragma unroll
        for (int ni = 0; ni < 4; ni++)
#pragma unroll
            for (int r = 0; r < 4; r++) acc[mi][ni][r] = 0.f;

    float4 pa[2], pb[2];
    // ---- prologue: fetch tile 0 ----
#pragma unroll
    for (int it = 0; it < 2; it++) {
        int lin = tid + it * 256;
        int m = lin >> 2, k4 = lin & 3;
        pa[it] = *reinterpret_cast<const float4*>(&A[(size_t)(r0 + m) * DM + k4 * 4]);
        pb[it] = *reinterpret_cast<const float4*>(&Bt[(size_t)(nc + m) * DM + k4 * 4]);
    }
#pragma unroll
    for (int it = 0; it < 2; it++) {
        int lin = tid + it * 256;
        int m = lin >> 2, k4 = lin & 3;
        uint32_t* da = &sA[0][m * PAD + k4 * 4];
        da[0] = f2tf32(pa[it].x); da[1] = f2tf32(pa[it].y);
        da[2] = f2tf32(pa[it].z); da[3] = f2tf32(pa[it].w);
        uint32_t* db = &sB[0][m * PAD + k4 * 4];
        db[0] = __float_as_uint(pb[it].x); db[1] = __float_as_uint(pb[it].y);
        db[2] = __float_as_uint(pb[it].z); db[3] = __float_as_uint(pb[it].w);
    }
    __syncthreads();

    int cur = 0;
    const int NT = DM / 16;
    for (int kt = 0; kt < NT; kt++) {
        if (kt + 1 < NT) {
            const int kc = (kt + 1) * 16;
#pragma unroll
            for (int it = 0; it < 2; it++) {
                int lin = tid + it * 256;
                int m = lin >> 2, k4 = lin & 3;
                pa[it] = *reinterpret_cast<const float4*>(
                    &A[(size_t)(r0 + m) * DM + kc + k4 * 4]);
                pb[it] = *reinterpret_cast<const float4*>(
                    &Bt[(size_t)(nc + m) * DM + kc + k4 * 4]);
            }
        }
        const uint32_t* cA = sA[cur];
        const uint32_t* cB = sB[cur];
#pragma unroll
        for (int ks = 0; ks < 2; ks++) {
            const int k0 = ks * 8;
            uint32_t a[4][4], b[4][2];
#pragma unroll
            for (int mi = 0; mi < 4; mi++) {
                const uint32_t* p = &cA[(wm + mi * 16 + lr) * PAD + k0 + lc];
                a[mi][0] = p[0];
                a[mi][1] = p[8 * PAD];
                a[mi][2] = p[4];
                a[mi][3] = p[8 * PAD + 4];
            }
#pragma unroll
            for (int ni = 0; ni < 4; ni++) {
                const uint32_t* p = &cB[(wn + ni * 8 + lr) * PAD + k0 + lc];
                b[ni][0] = p[0];
                b[ni][1] = p[4];
            }
#pragma unroll
            for (int mi = 0; mi < 4; mi++)
#pragma unroll
                for (int ni = 0; ni < 4; ni++)
                    mma_tf32(acc[mi][ni], a[mi], b[ni]);
        }
        if (kt + 1 < NT) {
            uint32_t* nA = sA[cur ^ 1];
            uint32_t* nB = sB[cur ^ 1];
#pragma unroll
            for (int it = 0; it < 2; it++) {
                int lin = tid + it * 256;
                int m = lin >> 2, k4 = lin & 3;
                uint32_t* da = &nA[m * PAD + k4 * 4];
                da[0] = f2tf32(pa[it].x); da[1] = f2tf32(pa[it].y);
                da[2] = f2tf32(pa[it].z); da[3] = f2tf32(pa[it].w);
                uint32_t* db = &nB[m * PAD + k4 * 4];
                db[0] = __float_as_uint(pb[it].x); db[1] = __float_as_uint(pb[it].y);
                db[2] = __float_as_uint(pb[it].z); db[3] = __float_as_uint(pb[it].w);
            }
        }
        __syncthreads();
        cur ^= 1;
    }

#pragma unroll
    for (int mi = 0; mi < 4; mi++) {
#pragma unroll
        for (int ni = 0; ni < 4; ni++) {
#pragma unroll
            for (int h = 0; h < 2; h++) {
                int row = r0 + wm + mi * 16 + lr + h * 8;
                int col = wn + ni * 8 + 2 * lc;
                float v0 = acc[mi][ni][h * 2 + 0];
                float v1 = acc[mi][ni][h * 2 + 1];
                if (mode == 0) {
                    float2 o = {v0 + bv[nc + col], v1 + bv[nc + col + 1]};
                    *reinterpret_cast<float2*>(
                        &g_V[(size_t)row * DM + nc + col]) = o;
                } else {
                    float w0 = v0 + g_bqk[col];
                    float w1 = v1 + g_bqk[col + 1];
                    float2 o = {w0, w1};
                    if (col < 64)
                        *reinterpret_cast<float2*>(&g_Q[(size_t)row * DK + col]) = o;
                    else
                        *reinterpret_cast<float2*>(
                            &g_K[(size_t)row * DK + (col - 64)]) = o;
                }
            }
        }
    }
}

// ===========================================================================
// score_kernel: one 128x128 causal tile of S = Q K^T / 8 per CTA.
// Double-buffered, 4 k-iterations (DK=64, BK=16).
// ===========================================================================
__global__ __launch_bounds__(256, 2) void score_kernel()
{
    __shared__ uint32_t sA[2][128 * PAD];
    __shared__ uint32_t sB[2][128 * PAD];

    int i = blockIdx.x;
    int qt = (int)((sqrtf(8.f * (float)i + 1.f) - 1.f) * 0.5f);
    while ((qt + 1) * (qt + 2) / 2 <= i) qt++;
    while (qt * (qt + 1) / 2 > i) qt--;
    const int kt = i - qt * (qt + 1) / 2;

    const int b     = blockIdx.y;
    const int qbase = b * S + qt * 128;
    const int kbase = b * S + kt * 128;

    const int tid  = threadIdx.x;
    const int wid  = tid >> 5;
    const int lane = tid & 31;
    const int wm   = (wid >> 2) * 64;
    const int wn   = (wid & 3) * 32;
    const int lr   = lane >> 2;
    const int lc   = lane & 3;

    float acc[4][4][4];
#pragma unroll
    for (int mi = 0; mi < 4; mi++)
#pragma unroll
        for (int ni = 0; ni < 4; ni++)
#pragma unroll
            for (int r = 0; r < 4; r++) acc[mi][ni][r] = 0.f;

    float4 pa[2], pb[2];
#pragma unroll
    for (int it = 0; it < 2; it++) {
        int lin = tid + it * 256;
        int m = lin >> 2, k4 = lin & 3;
        pa[it] = *reinterpret_cast<const float4*>(&g_Q[(size_t)(qbase + m) * DK + k4 * 4]);
        pb[it] = *reinterpret_cast<const float4*>(&g_K[(size_t)(kbase + m) * DK + k4 * 4]);
    }
#pragma unroll
    for (int it = 0; it < 2; it++) {
        int lin = tid + it * 256;
        int m = lin >> 2, k4 = lin & 3;
        uint32_t* da = &sA[0][m * PAD + k4 * 4];
        da[0] = f2tf32(pa[it].x); da[1] = f2tf32(pa[it].y);
        da[2] = f2tf32(pa[it].z); da[3] = f2tf32(pa[it].w);
        uint32_t* db = &sB[0][m * PAD + k4 * 4];
        db[0] = f2tf32(pb[it].x); db[1] = f2tf32(pb[it].y);
        db[2] = f2tf32(pb[it].z); db[3] = f2tf32(pb[it].w);
    }
    __syncthreads();

    int cur = 0;
    const int NT = DK / 16;   // 4
    for (int ktile = 0; ktile < NT; ktile++) {
        if (ktile + 1 < NT) {
            const int kc = (ktile + 1) * 16;
#pragma unroll
            for (int it = 0; it < 2; it++) {
                int lin = tid + it * 256;
                int m = lin >> 2, k4 = lin & 3;
                pa[it] = *reinterpret_cast<const float4*>(
                    &g_Q[(size_t)(qbase + m) * DK + kc + k4 * 4]);
                pb[it] = *reinterpret_cast<const float4*>(
                    &g_K[(size_t)(kbase + m) * DK + kc + k4 * 4]);
            }
        }
        const uint32_t* cA = sA[cur];
        const uint32_t* cB = sB[cur];
#pragma unroll
        for (int ks = 0; ks < 2; ks++) {
            const int k0 = ks * 8;
            uint32_t a[4][4], b2[4][2];
#pragma unroll
            for (int mi = 0; mi < 4; mi++) {
                const uint32_t* p = &cA[(wm + mi * 16 + lr) * PAD + k0 + lc];
                a[mi][0] = p[0];
                a[mi][1] = p[8 * PAD];
                a[mi][2] = p[4];
                a[mi][3] = p[8 * PAD + 4];
            }
#pragma unroll
            for (int ni = 0; ni < 4; ni++) {
                const uint32_t* p = &cB[(wn + ni * 8 + lr) * PAD + k0 + lc];
                b2[ni][0] = p[0];
                b2[ni][1] = p[4];
            }
#pragma unroll
            for (int mi = 0; mi < 4; mi++)
#pragma unroll
                for (int ni = 0; ni < 4; ni++)
                    mma_tf32(acc[mi][ni], a[mi], b2[ni]);
        }
        if (ktile + 1 < NT) {
            uint32_t* nA = sA[cur ^ 1];
            uint32_t* nB = sB[cur ^ 1];
#pragma unroll
            for (int it = 0; it < 2; it++) {
                int lin = tid + it * 256;
                int m = lin >> 2, k4 = lin & 3;
                uint32_t* da = &nA[m * PAD + k4 * 4];
                da[0] = f2tf32(pa[it].x); da[1] = f2tf32(pa[it].y);
                da[2] = f2tf32(pa[it].z); da[3] = f2tf32(pa[it].w);
                uint32_t* db = &nB[m * PAD + k4 * 4];
                db[0] = f2tf32(pb[it].x); db[1] = f2tf32(pb[it].y);
                db[2] = f2tf32(pb[it].z); db[3] = f2tf32(pb[it].w);
            }
        }
        __syncthreads();
        cur ^= 1;
    }

#pragma unroll
    for (int mi = 0; mi < 4; mi++) {
#pragma unroll
        for (int ni = 0; ni < 4; ni++) {
#pragma unroll
            for (int h = 0; h < 2; h++) {
                int qrow = qt * 128 + wm + mi * 16 + lr + h * 8;
                int kcol = kt * 128 + wn + ni * 8 + 2 * lc;
                float v0 = acc[mi][ni][h * 2 + 0] * 0.125f;
                float v1 = acc[mi][ni][h * 2 + 1] * 0.125f;
                if (kcol > qrow)     v0 = -1e30f;
                if (kcol + 1 > qrow) v1 = -1e30f;
                float2 o = {v0, v1};
                *reinterpret_cast<float2*>(
                    &g_P[(size_t)(b * S + qrow) * S + kcol]) = o;
            }
        }
    }
}

// ===========================================================================
// rowexp_kernel: warp per row.  m = max(row), P = exp(P - m), l = sum,
// zero pad region up to the 128-tile boundary.
// ===========================================================================
__global__ __launch_bounds__(256) void rowexp_kernel()
{
    const int tid  = threadIdx.x;
    const int wid  = tid >> 5;
    const int lane = tid & 31;
    const int row  = blockIdx.x * 8 + wid;
    const int q    = row & (S - 1);
    float* P = &g_P[(size_t)row * S];
    const int L    = q + 1;
    const int kend = ((q >> 7) + 1) << 7;

    float m = -1e30f;
    for (int j = lane; j < L; j += 32) m = fmaxf(m, P[j]);
#pragma unroll
    for (int off = 16; off > 0; off >>= 1)
        m = fmaxf(m, __shfl_xor_sync(0xffffffffu, m, off));

    float l = 0.f;
    for (int j = lane; j < L; j += 32) {
        float e = __expf(P[j] - m);
        P[j] = e;
        l += e;
    }
#pragma unroll
    for (int off = 16; off > 0; off >>= 1)
        l += __shfl_xor_sync(0xffffffffu, l, off);

    for (int j = L + lane; j < kend; j += 32) P[j] = 0.f;

    if (lane == 0) g_L[row] = l;
}

// ===========================================================================
// pv_kernel: O[128q x 128d tile] = (P_exp/l) @ V.  Causal k-loop.
// BM=128 BN=128 BK=16, double-buffered.  sP stride 20, sV [k][d] stride 136.
// ===========================================================================
#define STV 136
__global__ __launch_bounds__(256, 2) void pv_kernel(float* __restrict__ out)
{
    __shared__ uint32_t sP[2][128 * PAD];
    __shared__ uint32_t sV[2][16 * STV];

    const int qt    = blockIdx.x;
    const int dc0   = blockIdx.y * 128;
    const int b     = blockIdx.z;
    const int base  = b * S;
    const int qbase = base + qt * 128;

    const int tid  = threadIdx.x;
    const int wid  = tid >> 5;
    const int lane = tid & 31;
    const int wm   = (wid >> 2) * 64;
    const int wn   = (wid & 3) * 32;
    const int lr   = lane >> 2;
    const int lc   = lane & 3;

    float acc[4][4][4];
#pragma unroll
    for (int mi = 0; mi < 4; mi++)
#pragma unroll
        for (int ni = 0; ni < 4; ni++)
#pragma unroll
            for (int r = 0; r < 4; r++) acc[mi][ni][r] = 0.f;

    float4 pp[2], pv4[2];
#pragma unroll
    for (int it = 0; it < 2; it++) {
        int lin = tid + it * 256;
        int m = lin >> 2, k4 = lin & 3;
        pp[it] = *reinterpret_cast<const float4*>(
            &g_P[(size_t)(qbase + m) * S + k4 * 4]);
        int k = lin >> 5, d4 = lin & 31;
        pv4[it] = *reinterpret_cast<const float4*>(
            &g_V[(size_t)(base + k) * DM + dc0 + d4 * 4]);
    }
#pragma unroll
    for (int it = 0; it < 2; it++) {
        int lin = tid + it * 256;
        int m = lin >> 2, k4 = lin & 3;
        uint32_t* dp = &sP[0][m * PAD + k4 * 4];
        dp[0] = f2tf32(pp[it].x); dp[1] = f2tf32(pp[it].y);
        dp[2] = f2tf32(pp[it].z); dp[3] = f2tf32(pp[it].w);
        int k = lin >> 5, d4 = lin & 31;
        uint32_t* dv = &sV[0][k * STV + d4 * 4];
        dv[0] = f2tf32(pv4[it].x); dv[1] = f2tf32(pv4[it].y);
        dv[2] = f2tf32(pv4[it].z); dv[3] = f2tf32(pv4[it].w);
    }
    __syncthreads();

    int cur = 0;
    const int NT = (qt + 1) * 8;      // (qt+1)*128 / 16
    for (int kt = 0; kt < NT; kt++) {
        if (kt + 1 < NT) {
            const int kc = (kt + 1) * 16;
#pragma unroll
            for (int it = 0; it < 2; it++) {
                int lin = tid + it * 256;
                int m = lin >> 2, k4 = lin & 3;
                pp[it] = *reinterpret_cast<const float4*>(
                    &g_P[(size_t)(qbase + m) * S + kc + k4 * 4]);
                int k = lin >> 5, d4 = lin & 31;
                pv4[it] = *reinterpret_cast<const float4*>(
                    &g_V[(size_t)(base + kc + k) * DM + dc0 + d4 * 4]);
            }
        }
        const uint32_t* cP = sP[cur];
        const uint32_t* cV = sV[cur];
#pragma unroll
        for (int ks = 0; ks < 2; ks++) {
            const int k0 = ks * 8;
            uint32_t a[4][4], b2[4][2];
#pragma unroll
            for (int mi = 0; mi < 4; mi++) {
                const uint32_t* p = &cP[(wm + mi * 16 + lr) * PAD + k0 + lc];
                a[mi][0] = p[0];
                a[mi][1] = p[8 * PAD];
                a[mi][2] = p[4];
                a[mi][3] = p[8 * PAD + 4];
            }
#pragma unroll
            for (int ni = 0; ni < 4; ni++) {
                int n = wn + ni * 8 + lr;
                b2[ni][0] = cV[(k0 + lc) * STV + n];
                b2[ni][1] = cV[(k0 + lc + 4) * STV + n];
            }
#pragma unroll
            for (int mi = 0; mi < 4; mi++)
#pragma unroll
                for (int ni = 0; ni < 4; ni++)
                    mma_tf32(acc[mi][ni], a[mi], b2[ni]);
        }
        if (kt + 1 < NT) {
            uint32_t* nP = sP[cur ^ 1];
            uint32_t* nV = sV[cur ^ 1];
#pragma unroll
            for (int it = 0; it < 2; it++) {
                int lin = tid + it * 256;
                int m = lin >> 2, k4 = lin & 3;
                uint32_t* dp = &nP[m * PAD + k4 * 4];
                dp[0] = f2tf32(pp[it].x); dp[1] = f2tf32(pp[it].y);
                dp[2] = f2tf32(pp[it].z); dp[3] = f2tf32(pp[it].w);
                int k = lin >> 5, d4 = lin & 31;
                uint32_t* dv = &nV[k * STV + d4 * 4];
                dv[0] = f2tf32(pv4[it].x); dv[1] = f2tf32(pv4[it].y);
                dv[2] = f2tf32(pv4[it].z); dv[3] = f2tf32(pv4[it].w);
            }
        }
        __syncthreads();
        cur ^= 1;
    }

#pragma unroll
    for (int mi = 0; mi < 4; mi++) {
#pragma unroll
        for (int h = 0; h < 2; h++) {
            int qrow = qt * 128 + wm + mi * 16 + lr + h * 8;
            float linv = 1.0f / g_L[base + qrow];
#pragma unroll
            for (int ni = 0; ni < 4; ni++) {
                int col = dc0 + wn + ni * 8 + 2 * lc;
                float2 o = {acc[mi][ni][h * 2 + 0] * linv,
                            acc[mi][ni][h * 2 + 1] * linv};
                *reinterpret_cast<float2*>(
                    &out[(size_t)(base + qrow) * DM + col]) = o;
            }
        }
    }
}

// ===========================================================================
extern "C" void kernel_launch(void* const* d_in, const int* in_sizes, int n_in,
                              void* d_out, int out_size)
{
    const float* X  = (const float*)d_in[0];
    const float* Wq = (const float*)d_in[1];
    const float* bq = (const float*)d_in[2];
    const float* Wk = (const float*)d_in[3];
    const float* bk = (const float*)d_in[4];
    const float* Wv = (const float*)d_in[5];
    const float* bv = (const float*)d_in[6];
    float* out = (float*)d_out;

    transpose_wv_kernel<<<dim3(32, 32), dim3(32, 8)>>>(Wv);
    prep_qk_kernel<<<dim3(32, 4), dim3(32, 8)>>>(Wq, bq, Wk, bk);
    gemm_tc_kernel<<<dim3(128, 1), 256>>>(X, nullptr, 1);   // Q|K projection
    gemm_tc_kernel<<<dim3(128, 8), 256>>>(X, bv, 0);        // V projection
    score_kernel<<<dim3(136, 8), 256>>>();                  // S = QK^T/8 (causal)
    rowexp_kernel<<<ROWS / 8, 256>>>();                     // softmax (in place)
    pv_kernel<<<dim3(S / 128, DM / 128, B), 256>>>(out);    // O = P V / l
}